// round 9
// baseline (speedup 1.0000x reference)
#include <cuda_runtime.h>
#include <cstdint>

// SliceLSTM persistent kernel, round 9: two batch-groups software-pipelined.
// B=64, T=512, S=4, DIN=64, H=128, HTOT=512.
// 128 CTAs x 256 threads, clusters of 4 = (gate g2, K-chunk kc), rank = tile.
// Batches split into groups g in {0,1} (b 0-31 / 32-63); per step the phases
// interleave g0/g1 so every cross-SM wait is hidden behind the other group's
// compute. Act exchanged in-cluster via st.shared::cluster (parity slots);
// partials and h flow via L2 with per-(group,tile) release counters.

#define NCTA 128
#define NTHR 256

typedef unsigned long long u64;

// shared layout (float offsets)
#define OFF_W1  0        // 192 x 16
#define OFF_B1  3072     // 16
#define OFF_W2  3088     // 64 x 128
#define OFF_X   11280    // [64 k][LDX] both groups, k-major
#define LDX     66
#define OFF_H   15504    // [128 k][LDH] one group at a time, k-major
#define LDH     34
#define OFF_ACT 19856    // [2 parity][64 k][LDA] both groups' columns
#define LDA     66
#define ACT_PAR (64 * LDA)
#define SMEM_BYTES 118784   // 116KB -> 1 CTA/SM

__device__ float g_hbuf[2][2][32 * 512];          // [parity][grp][b][c]
__device__ float g_part[2][2][NCTA * 32 * 128];   // [parity][grp][cta][b][cl]
__device__ unsigned g_pcnt[8 * 64];               // (grp*4+tile)*64, 256B apart
__device__ unsigned g_hcnt[8 * 64];

static __device__ __forceinline__ u64 pk2(float v) {
    u64 r; asm("mov.b64 %0, {%1, %1};" : "=l"(r) : "f"(v)); return r;
}
static __device__ __forceinline__ void unp2(u64 v, float& lo, float& hi) {
    asm("mov.b64 {%0, %1}, %2;" : "=f"(lo), "=f"(hi) : "l"(v));
}
static __device__ __forceinline__ u64 pkab(float lo, float hi) {
    u64 r; asm("mov.b64 %0, {%1, %2};" : "=l"(r) : "f"(lo), "f"(hi)); return r;
}
static __device__ __forceinline__ void fma2(u64& d, u64 a, u64 b) {
    asm("fma.rn.f32x2 %0, %1, %2, %0;" : "+l"(d) : "l"(a), "l"(b));
}
static __device__ __forceinline__ u64 add2(u64 a, u64 b) {
    u64 r; asm("add.rn.f32x2 %0, %1, %2;" : "=l"(r) : "l"(a), "l"(b)); return r;
}
static __device__ __forceinline__ float sigf(float x)  { return 1.0f / (1.0f + __expf(-x)); }
static __device__ __forceinline__ float tanhe(float x) {
    float e = __expf(2.0f * x);
    return 1.0f - 2.0f / (e + 1.0f);
}
static __device__ __forceinline__ unsigned ldacq(const unsigned* p) {
    unsigned v;
    asm volatile("ld.acquire.gpu.global.u32 %0, [%1];" : "=r"(v) : "l"(p) : "memory");
    return v;
}
static __device__ __forceinline__ void redrel(unsigned* p) {
    asm volatile("red.release.gpu.global.add.u32 [%0], 1;" :: "l"(p) : "memory");
}
static __device__ __forceinline__ uint32_t smem_u32(const void* p) {
    uint32_t a;
    asm("{ .reg .u64 t; cvta.to.shared.u64 t, %1; cvt.u32.u64 %0, t; }" : "=r"(a) : "l"(p));
    return a;
}
static __device__ __forceinline__ uint32_t mapa_rank(uint32_t addr, int rank) {
    uint32_t r;
    asm("mapa.shared::cluster.u32 %0, %1, %2;" : "=r"(r) : "r"(addr), "r"(rank));
    return r;
}
static __device__ __forceinline__ void st_cluster64(uint32_t addr, u64 v) {
    asm volatile("st.shared::cluster.u64 [%0], %1;" :: "r"(addr), "l"(v) : "memory");
}
#define CARRIVE() asm volatile("barrier.cluster.arrive.aligned;" ::: "memory")
#define CWAIT()   asm volatile("barrier.cluster.wait.aligned;" ::: "memory")

__global__ void zero_kernel() {
    int i = blockIdx.x * blockDim.x + threadIdx.x;
    int n = blockDim.x * gridDim.x;
    for (int j = i; j < 2 * 16384; j += n) ((float*)g_hbuf)[j] = 0.0f;  // parity 0
    for (int j = i; j < 8 * 64; j += n) { g_pcnt[j] = 0u; g_hcnt[j] = 0u; }
}

__global__ void __launch_bounds__(NTHR, 1) __cluster_dims__(4, 1, 1)
slstm_kernel(const float* __restrict__ x,       // (64, 512, 256)
             const float* __restrict__ Ws,      // (4, 64, 512)
             const float* __restrict__ Us,      // (4, 128, 512)
             const float* __restrict__ biases,  // (4, 512)
             const float* __restrict__ Wc,      // (512, 2048)
             const float* __restrict__ bc,      // (2048,)
             float* __restrict__ out)           // hseq | h_t | c_t
{
    extern __shared__ float sm[];
    float* sW1  = sm + OFF_W1;
    float* sB1  = sm + OFF_B1;
    float* sW2  = sm + OFF_W2;
    float* sX   = sm + OFF_X;
    float* sH   = sm + OFF_H;
    float* sAct = sm + OFF_ACT;

    const int tid  = threadIdx.x;
    const int cta  = blockIdx.x;
    const int rank = cta & 3;
    const int clu  = cta >> 2;        // 0..31
    const int g2   = clu >> 3;        // gate
    const int kc   = clu & 7;         // connector K-chunk
    const int s1   = kc >> 1;         // input slice
    const int wcol0 = g2 * 128 + (kc & 1) * 64 + rank * 16;

    // P1 role: col c1 (0..15), batch-pair bp1 (0..15) -> b = 2*bp1, 2*bp1+1
    const int c1  = tid & 15;
    const int bp1 = tid >> 4;
    // P2 role: batch-pair bp2, col-group cg2 (8 cols)
    const int bp2 = tid & 15;
    const int cg2 = tid >> 4;
    // P3 role: group = tid>>7, col l3 = tid&127, batch = clu (within group)
    const int gp3 = tid >> 7;
    const int l3  = tid & 127;
    const int colg = rank * 128 + l3;

    // ---- persistent weights ----
    for (int i = tid; i < 192 * 16; i += NTHR) {
        int k = i >> 4, c = i & 15;
        sW1[i] = (k < 64) ? Ws[s1 * (64 * 512) + k * 512 + wcol0 + c]
                          : Us[s1 * (128 * 512) + (k - 64) * 512 + wcol0 + c];
    }
    if (tid < 16) sB1[tid] = biases[s1 * 512 + wcol0 + tid];
    for (int i = tid; i < 64 * 128; i += NTHR) {
        int k = i >> 7, c = i & 127;
        sW2[k * 128 + c] = Wc[(kc * 64 + k) * 2048 + g2 * 512 + rank * 128 + c];
    }

    // P3 biases + per-thread cell state (one (group,b,col) per thread)
    const float bci = bc[colg];
    const float bcf = bc[512 + colg];
    const float bcg = bc[1024 + colg];
    const float bco = bc[1536 + colg];
    float creg = 0.0f, hlast = 0.0f;

    // stage x(t=0), k-major, both groups
    for (int i = tid; i < 1024; i += NTHR) {
        int b = i & 63, q = i >> 6;
        float4 v = __ldg(reinterpret_cast<const float4*>(
            &x[b * (512 * 256) + s1 * 64 + q * 4]));
        sX[(q * 4 + 0) * LDX + b] = v.x;
        sX[(q * 4 + 1) * LDX + b] = v.y;
        sX[(q * 4 + 2) * LDX + b] = v.z;
        sX[(q * 4 + 3) * LDX + b] = v.w;
    }
    const uint32_t act_u32 = smem_u32(sAct);

    for (int t = 0; t < 512; ++t) {
        const int p  = t & 1;
        const int pn = p ^ 1;
        const int par = p;
        u64 actpk[2];   // activated act packed, per group

        #pragma unroll
        for (int g = 0; g < 2; ++g) {
            // --- wait h(g), stage k-major ---
            if (tid == 0) {
                const unsigned need = 32u * (unsigned)t;
                while (ldacq(&g_hcnt[(g * 4 + s1) * 64]) < need) {}
            }
            __syncthreads();
            const float* hb = g_hbuf[p][g];
            for (int i = tid; i < 1024; i += NTHR) {
                int b = i & 31, q = i >> 5;
                float4 v = __ldcg(reinterpret_cast<const float4*>(
                    &hb[b * 512 + s1 * 128 + q * 4]));
                sH[(q * 4 + 0) * LDH + b] = v.x;
                sH[(q * 4 + 1) * LDH + b] = v.y;
                sH[(q * 4 + 2) * LDH + b] = v.z;
                sH[(q * 4 + 3) * LDH + b] = v.w;
            }
            __syncthreads();
            // --- P1 GEMM(g): batch-pair packed, 1 col x 2 b per thread ---
            {
                const int gb0 = g * 32 + 2 * bp1;
                const float* wp = sW1 + c1;
                u64 a0c = 0ULL, a1c = 0ULL;
                #pragma unroll 4
                for (int k = 0; k < 64; k += 2) {
                    u64 a0 = *reinterpret_cast<const u64*>(&sX[k * LDX + gb0]);
                    u64 a1 = *reinterpret_cast<const u64*>(&sX[(k + 1) * LDX + gb0]);
                    fma2(a0c, a0, pk2(wp[k * 16]));
                    fma2(a1c, a1, pk2(wp[(k + 1) * 16]));
                }
                #pragma unroll 4
                for (int k = 0; k < 128; k += 2) {
                    u64 a0 = *reinterpret_cast<const u64*>(&sH[k * LDH + 2 * bp1]);
                    u64 a1 = *reinterpret_cast<const u64*>(&sH[(k + 1) * LDH + 2 * bp1]);
                    fma2(a0c, a0, pk2(wp[(64 + k) * 16]));
                    fma2(a1c, a1, pk2(wp[(65 + k) * 16]));
                }
                float f0, f1;
                unp2(add2(a0c, a1c), f0, f1);
                const float bias = sB1[c1];
                f0 += bias; f1 += bias;
                if (g2 == 2) { f0 = tanhe(f0); f1 = tanhe(f1); }
                else         { f0 = sigf(f0);  f1 = sigf(f1);  }
                actpk[g] = pkab(f0, f1);
            }
            if (g == 0) {
                // store act(g0) local+remote, then arrive phase A
                const int off = par * ACT_PAR + (rank * 16 + c1) * LDA + 2 * bp1;
                *reinterpret_cast<u64*>(&sAct[off]) = actpk[0];
                const uint32_t la = act_u32 + off * 4;
                #pragma unroll
                for (int r = 0; r < 4; ++r) {
                    if (r == rank) continue;
                    st_cluster64(mapa_rank(la, r), actpk[0]);
                }
                CARRIVE();
            }
        }
        // act(g0) fully present after peers arrive
        CWAIT();
        {   // store act(g1) local+remote, arrive phase B
            const int off = par * ACT_PAR + (rank * 16 + c1) * LDA + 32 + 2 * bp1;
            *reinterpret_cast<u64*>(&sAct[off]) = actpk[1];
            const uint32_t la = act_u32 + off * 4;
            #pragma unroll
            for (int r = 0; r < 4; ++r) {
                if (r == rank) continue;
                st_cluster64(mapa_rank(la, r), actpk[1]);
            }
        }
        CARRIVE();

        // --- P2 GEMM(g0) ---
        #pragma unroll
        for (int g = 0; g < 2; ++g) {
            if (g == 1) CWAIT();   // act(g1) ready
            const float* ab = sAct + par * ACT_PAR + g * 32 + 2 * bp2;
            const float* wb = sW2 + cg2 * 8;
            u64 acc[2][4];
            #pragma unroll
            for (int i = 0; i < 2; ++i)
                #pragma unroll
                for (int j = 0; j < 4; ++j) acc[i][j] = 0ULL;
            #pragma unroll 4
            for (int k = 0; k < 64; ++k) {
                float2 a2 = *reinterpret_cast<const float2*>(&ab[k * LDA]);
                const u64 a0 = pk2(a2.x);
                const u64 a1 = pk2(a2.y);
                const ulonglong2 wA = *reinterpret_cast<const ulonglong2*>(&wb[k * 128]);
                const ulonglong2 wB = *reinterpret_cast<const ulonglong2*>(&wb[k * 128 + 4]);
                fma2(acc[0][0], a0, wA.x); fma2(acc[0][1], a0, wA.y);
                fma2(acc[0][2], a0, wB.x); fma2(acc[0][3], a0, wB.y);
                fma2(acc[1][0], a1, wA.x); fma2(acc[1][1], a1, wA.y);
                fma2(acc[1][2], a1, wB.x); fma2(acc[1][3], a1, wB.y);
            }
            float* pp = &g_part[p][g][cta * 4096 + (2 * bp2) * 128 + cg2 * 8];
            #pragma unroll
            for (int i = 0; i < 2; ++i) {
                float q0, q1, q2, q3, q4, q5, q6, q7;
                unp2(acc[i][0], q0, q1); unp2(acc[i][1], q2, q3);
                unp2(acc[i][2], q4, q5); unp2(acc[i][3], q6, q7);
                float4* d = reinterpret_cast<float4*>(pp + i * 128);
                __stcg(d, make_float4(q0, q1, q2, q3));
                __stcg(d + 1, make_float4(q4, q5, q6, q7));
            }
            __syncthreads();
            if (tid == 0) {
                __threadfence();
                redrel(&g_pcnt[(g * 4 + rank) * 64]);
            }
        }

        // --- P3(g0) + x prefetch; then P3(g1) ---
        #pragma unroll
        for (int g = 0; g < 2; ++g) {
            if (tid == 0) {
                const unsigned need = 32u * (unsigned)(t + 1);
                while (ldacq(&g_pcnt[(g * 4 + rank) * 64]) < need) {}
            }
            __syncthreads();
            if (gp3 == g) {
                float s0 = bci, s1v = bcf, s2 = bcg, s3 = bco;
                const float* pb = &g_part[p][g][clu * 128 + l3];
                #pragma unroll
                for (int j = 0; j < 8; ++j) {
                    s0  += __ldcg(pb + ((0 * 8 + j) * 4 + rank) * 4096);
                    s1v += __ldcg(pb + ((1 * 8 + j) * 4 + rank) * 4096);
                    s2  += __ldcg(pb + ((2 * 8 + j) * 4 + rank) * 4096);
                    s3  += __ldcg(pb + ((3 * 8 + j) * 4 + rank) * 4096);
                }
                const float iv = sigf(s0);
                const float fv = sigf(s1v);
                const float gv = tanhe(s2);
                const float ov = sigf(s3);
                creg = fv * creg + iv * gv;
                const float hn = ov * tanhe(creg);
                hlast = hn;
                __stcg(&g_hbuf[pn][g][clu * 512 + colg], hn);
                out[(g * 32 + clu) * (512 * 512) + t * 512 + colg] = hn;
            } else if (g == 0 && t + 1 < 512) {
                // other half prefetches x(t+1)
                for (int i = l3; i < 1024; i += 128) {
                    int b = i & 63, q = i >> 6;
                    float4 v = __ldg(reinterpret_cast<const float4*>(
                        &x[b * (512 * 256) + (t + 1) * 256 + s1 * 64 + q * 4]));
                    sX[(q * 4 + 0) * LDX + b] = v.x;
                    sX[(q * 4 + 1) * LDX + b] = v.y;
                    sX[(q * 4 + 2) * LDX + b] = v.z;
                    sX[(q * 4 + 3) * LDX + b] = v.w;
                }
            }
            __syncthreads();
            if (tid == 0) {
                __threadfence();
                redrel(&g_hcnt[(g * 4 + rank) * 64]);
            }
        }
    }

    // final h_t and c_t (each thread owns one (group, batch, col))
    out[16777216 + (gp3 * 32 + clu) * 512 + colg] = hlast;
    out[16777216 + 32768 + (gp3 * 32 + clu) * 512 + colg] = creg;
}

extern "C" void kernel_launch(void* const* d_in, const int* in_sizes, int n_in,
                              void* d_out, int out_size) {
    const float* x      = (const float*)d_in[0];
    const float* Ws     = (const float*)d_in[1];
    const float* Us     = (const float*)d_in[2];
    const float* biases = (const float*)d_in[3];
    const float* Wc     = (const float*)d_in[4];
    const float* bc     = (const float*)d_in[5];
    float* out = (float*)d_out;
    (void)in_sizes; (void)n_in; (void)out_size;

    zero_kernel<<<32, 256>>>();
    cudaFuncSetAttribute(slstm_kernel, cudaFuncAttributeMaxDynamicSharedMemorySize,
                         SMEM_BYTES);
    slstm_kernel<<<NCTA, NTHR, SMEM_BYTES>>>(x, Ws, Us, biases, Wc, bc, out);
}

// round 10
// speedup vs baseline: 1.2828x; 1.2828x over previous
#include <cuda_runtime.h>
#include <cstdint>

// SliceLSTM persistent kernel, round 10 = R8 + latency cuts.
// 128 CTAs x 256 threads, clusters of 4 = (gate, K-chunk), rank = tile.
// cp.async for h staging (overlapped with x-GEMM) and x(t+1) (issued at step
// start, parity double-buffered). Act parity-buffered: 1 cluster barrier/step.
// Partials + h via L2 with release counters (R8 protocol).

#define NCTA 128
#define NTHR 256

typedef unsigned long long u64;

// shared layout (float offsets)
#define OFF_W1  0         // 192 x 16
#define OFF_B1  3072      // 16
#define OFF_W2  3088      // 64 x 128
#define OFF_X   11280     // [2 parity][64 b][68]  (x, b-major)
#define LDXR    68
#define XPAR    (64 * LDXR)
#define OFF_H   19984     // [64 b][132]           (h, b-major)
#define LDHR    132
#define OFF_ACT 28432     // [2 parity][64 c][68]  (act, k-major)
#define LDA     68
#define APAR    (64 * LDA)
#define SMEM_FLOATS 37136
#define SMEM_BYTES  (SMEM_FLOATS * 4)   // 145.1KB -> 1 CTA/SM

__device__ float g_hbuf[2][64 * 512];           // [parity][b][c]
__device__ float g_part[2][NCTA * 64 * 128];    // [parity][cta][b][cl]
__device__ unsigned g_pcnt[4 * 64];             // per tile, 256B apart
__device__ unsigned g_hcnt[4 * 64];

static __device__ __forceinline__ u64 pk2(float v) {
    u64 r; asm("mov.b64 %0, {%1, %1};" : "=l"(r) : "f"(v)); return r;
}
static __device__ __forceinline__ void unp2(u64 v, float& lo, float& hi) {
    asm("mov.b64 {%0, %1}, %2;" : "=f"(lo), "=f"(hi) : "l"(v));
}
static __device__ __forceinline__ void fma2(u64& d, u64 a, u64 b) {
    asm("fma.rn.f32x2 %0, %1, %2, %0;" : "+l"(d) : "l"(a), "l"(b));
}
static __device__ __forceinline__ float sigf(float x)  { return 1.0f / (1.0f + __expf(-x)); }
static __device__ __forceinline__ float tanhe(float x) {
    float e = __expf(2.0f * x);
    return 1.0f - 2.0f / (e + 1.0f);
}
static __device__ __forceinline__ unsigned ldacq(const unsigned* p) {
    unsigned v;
    asm volatile("ld.acquire.gpu.global.u32 %0, [%1];" : "=r"(v) : "l"(p) : "memory");
    return v;
}
static __device__ __forceinline__ void redrel(unsigned* p) {
    asm volatile("red.release.gpu.global.add.u32 [%0], 1;" :: "l"(p) : "memory");
}
static __device__ __forceinline__ uint32_t smem_u32(const void* p) {
    uint32_t a;
    asm("{ .reg .u64 t; cvta.to.shared.u64 t, %1; cvt.u32.u64 %0, t; }" : "=r"(a) : "l"(p));
    return a;
}
static __device__ __forceinline__ uint32_t mapa_rank(uint32_t addr, int rank) {
    uint32_t r;
    asm("mapa.shared::cluster.u32 %0, %1, %2;" : "=r"(r) : "r"(addr), "r"(rank));
    return r;
}
static __device__ __forceinline__ void st_cluster(uint32_t addr, float v) {
    asm volatile("st.shared::cluster.f32 [%0], %1;" :: "r"(addr), "f"(v) : "memory");
}
static __device__ __forceinline__ void cpasync16(uint32_t dst, const float* src) {
    asm volatile("cp.async.cg.shared.global [%0], [%1], 16;" :: "r"(dst), "l"(src) : "memory");
}
#define CP_COMMIT() asm volatile("cp.async.commit_group;" ::: "memory")
#define CP_WAIT0()  asm volatile("cp.async.wait_group 0;" ::: "memory")
#define CARRIVE() asm volatile("barrier.cluster.arrive.aligned;" ::: "memory")
#define CWAIT()   asm volatile("barrier.cluster.wait.aligned;" ::: "memory")

__global__ void zero_kernel() {
    int i = blockIdx.x * blockDim.x + threadIdx.x;
    int n = blockDim.x * gridDim.x;
    for (int j = i; j < 64 * 512; j += n) g_hbuf[0][j] = 0.0f;
    for (int j = i; j < 4 * 64; j += n) { g_pcnt[j] = 0u; g_hcnt[j] = 0u; }
}

__global__ void __launch_bounds__(NTHR, 1) __cluster_dims__(4, 1, 1)
slstm_kernel(const float* __restrict__ x,       // (64, 512, 256)
             const float* __restrict__ Ws,      // (4, 64, 512)
             const float* __restrict__ Us,      // (4, 128, 512)
             const float* __restrict__ biases,  // (4, 512)
             const float* __restrict__ Wc,      // (512, 2048)
             const float* __restrict__ bc,      // (2048,)
             float* __restrict__ out)           // hseq | h_t | c_t
{
    extern __shared__ float sm[];
    float* sW1  = sm + OFF_W1;
    float* sB1  = sm + OFF_B1;
    float* sW2  = sm + OFF_W2;
    float* sX   = sm + OFF_X;
    float* sH   = sm + OFF_H;
    float* sAct = sm + OFF_ACT;

    const int tid  = threadIdx.x;
    const int cta  = blockIdx.x;
    const int rank = cta & 3;
    const int clu  = cta >> 2;        // 0..31
    const int g2   = clu >> 3;        // gate
    const int kc   = clu & 7;         // connector K-chunk
    const int s1   = kc >> 1;         // input slice
    const int wcol0 = g2 * 128 + (kc & 1) * 64 + rank * 16;

    // P1 role: 1 batch x 4 cols per thread
    const int pab = tid >> 2;
    const int pac = tid & 3;
    // P2 role: 4 batches x 8 cols per thread (all 256 threads)
    const int b20 = (tid & 15) * 4;
    const int cg2 = tid >> 4;          // 0..15
    // P3 role (tid<64)
    const int b0p  = clu * 2;
    const int boff = (tid >> 5) & 1;
    const int c4   = (tid & 31) * 4;

    // ---- persistent weights ----
    for (int i = tid; i < 192 * 16; i += NTHR) {
        int k = i >> 4, c = i & 15;
        sW1[i] = (k < 64) ? Ws[s1 * (64 * 512) + k * 512 + wcol0 + c]
                          : Us[s1 * (128 * 512) + (k - 64) * 512 + wcol0 + c];
    }
    if (tid < 16) sB1[tid] = biases[s1 * 512 + wcol0 + tid];
    for (int i = tid; i < 64 * 128; i += NTHR) {
        int k = i >> 7, c = i & 127;
        sW2[k * 128 + c] = Wc[(kc * 64 + k) * 2048 + g2 * 512 + rank * 128 + c];
    }

    // P3 biases + state
    float4 bi = {0,0,0,0}, bf = {0,0,0,0}, bg4 = {0,0,0,0}, bo = {0,0,0,0};
    float4 creg = {0,0,0,0}, hlast = {0,0,0,0};
    if (tid < 64) {
        const int ccl = rank * 128 + c4;
        bi  = *reinterpret_cast<const float4*>(&bc[ccl]);
        bf  = *reinterpret_cast<const float4*>(&bc[512 + ccl]);
        bg4 = *reinterpret_cast<const float4*>(&bc[1024 + ccl]);
        bo  = *reinterpret_cast<const float4*>(&bc[1536 + ccl]);
    }

    const uint32_t xs_u32  = smem_u32(sX);
    const uint32_t hs_u32  = smem_u32(sH);
    const uint32_t act_u32 = smem_u32(sAct);
    uint32_t peer[4];
    #pragma unroll
    for (int r = 0; r < 4; ++r) peer[r] = mapa_rank(act_u32, r);

    // stage x(t=0) into parity 0
    {
        #pragma unroll
        for (int j = 0; j < 4; ++j) {
            int lin = tid + 256 * j;           // 0..1023
            int b = lin & 63, q = lin >> 6;    // q 0..15
            cpasync16(xs_u32 + (b * LDXR + q * 4) * 4,
                      &x[b * (512 * 256) + s1 * 64 + q * 4]);
        }
        CP_COMMIT();
        CP_WAIT0();
    }
    __syncthreads();

    for (int t = 0; t < 512; ++t) {
        const int p  = t & 1;
        const int pn = p ^ 1;

        // --- (1) issue x(t+1) prefetch into sX[pn] ---
        if (t + 1 < 512) {
            #pragma unroll
            for (int j = 0; j < 4; ++j) {
                int lin = tid + 256 * j;
                int b = lin & 63, q = lin >> 6;
                cpasync16(xs_u32 + (pn * XPAR + b * LDXR + q * 4) * 4,
                          &x[b * (512 * 256) + (t + 1) * 256 + s1 * 64 + q * 4]);
            }
        }
        CP_COMMIT();

        // --- (2) wait h-flag ---
        if (tid == 0) {
            const unsigned need = 32u * (unsigned)t;
            while (ldacq(&g_hcnt[s1 * 64]) < need) {}
        }
        __syncthreads();

        // --- (3) issue h cp.async (L2-direct) ---
        {
            const float* hb = g_hbuf[p];
            #pragma unroll
            for (int j = 0; j < 8; ++j) {
                int lin = tid + 256 * j;           // 0..2047
                int b = lin & 63, q = lin >> 6;    // q 0..31
                cpasync16(hs_u32 + (b * LDHR + q * 4) * 4,
                          &hb[b * 512 + s1 * 128 + q * 4]);
            }
        }
        CP_COMMIT();

        // --- (4) P1 x-part GEMM while h lands ---
        u64 acc0 = 0ULL, acc1 = 0ULL;
        {
            const float* ap = sX + p * XPAR + pab * LDXR;
            const float* wp = sW1 + pac * 4;
            #pragma unroll 8
            for (int k = 0; k < 64; ++k) {
                const ulonglong2 w = *reinterpret_cast<const ulonglong2*>(wp + k * 16);
                const u64 a = pk2(ap[k]);
                fma2(acc0, a, w.x);
                fma2(acc1, a, w.y);
            }
        }
        CP_WAIT0();          // x(t+1) + h both resident
        __syncthreads();

        // --- (5) P1 h-part GEMM + activation ---
        float v0, v1, v2, v3;
        {
            const float* ap = sH + pab * LDHR;
            const float* wp = sW1 + pac * 4;
            #pragma unroll 8
            for (int k = 0; k < 128; ++k) {
                const ulonglong2 w = *reinterpret_cast<const ulonglong2*>(wp + (64 + k) * 16);
                const u64 a = pk2(ap[k]);
                fma2(acc0, a, w.x);
                fma2(acc1, a, w.y);
            }
            unp2(acc0, v0, v1);
            unp2(acc1, v2, v3);
            v0 += sB1[pac * 4 + 0];
            v1 += sB1[pac * 4 + 1];
            v2 += sB1[pac * 4 + 2];
            v3 += sB1[pac * 4 + 3];
            if (g2 == 2) { v0 = tanhe(v0); v1 = tanhe(v1); v2 = tanhe(v2); v3 = tanhe(v3); }
            else         { v0 = sigf(v0);  v1 = sigf(v1);  v2 = sigf(v2);  v3 = sigf(v3);  }
        }

        // --- (6) act publish local + remote, one cluster barrier ---
        {
            const int lc = rank * 16 + pac * 4;
            const int base = p * APAR + lc * LDA + pab;
            sAct[base]           = v0;
            sAct[base + LDA]     = v1;
            sAct[base + 2 * LDA] = v2;
            sAct[base + 3 * LDA] = v3;
            const uint32_t off = (uint32_t)base * 4;
            #pragma unroll
            for (int r = 0; r < 4; ++r) {
                if (r == rank) continue;
                const uint32_t ra = peer[r] + off;
                st_cluster(ra,               v0);
                st_cluster(ra + 4 * LDA,     v1);
                st_cluster(ra + 8 * LDA,     v2);
                st_cluster(ra + 12 * LDA,    v3);
            }
        }
        CARRIVE();
        CWAIT();

        // --- (7) P2 connector GEMM (all 256 threads) ---
        {
            u64 acc[4][4];
            #pragma unroll
            for (int i = 0; i < 4; ++i)
                #pragma unroll
                for (int j = 0; j < 4; ++j) acc[i][j] = 0ULL;
            const float* ab = sAct + p * APAR;
            const float* wb = sW2 + cg2 * 8;
            #pragma unroll 4
            for (int k = 0; k < 64; ++k) {
                const float4 a4 = *reinterpret_cast<const float4*>(&ab[k * LDA + b20]);
                const ulonglong2 wA = *reinterpret_cast<const ulonglong2*>(&wb[k * 128]);
                const ulonglong2 wB = *reinterpret_cast<const ulonglong2*>(&wb[k * 128 + 4]);
                const u64 a0 = pk2(a4.x);
                const u64 a1 = pk2(a4.y);
                const u64 a2 = pk2(a4.z);
                const u64 a3 = pk2(a4.w);
                fma2(acc[0][0], a0, wA.x); fma2(acc[0][1], a0, wA.y);
                fma2(acc[0][2], a0, wB.x); fma2(acc[0][3], a0, wB.y);
                fma2(acc[1][0], a1, wA.x); fma2(acc[1][1], a1, wA.y);
                fma2(acc[1][2], a1, wB.x); fma2(acc[1][3], a1, wB.y);
                fma2(acc[2][0], a2, wA.x); fma2(acc[2][1], a2, wA.y);
                fma2(acc[2][2], a2, wB.x); fma2(acc[2][3], a2, wB.y);
                fma2(acc[3][0], a3, wA.x); fma2(acc[3][1], a3, wA.y);
                fma2(acc[3][2], a3, wB.x); fma2(acc[3][3], a3, wB.y);
            }
            float* pp = g_part[p] + cta * 8192 + cg2 * 8;
            #pragma unroll
            for (int i = 0; i < 4; ++i) {
                float q0, q1, q2, q3, q4, q5, q6, q7;
                unp2(acc[i][0], q0, q1); unp2(acc[i][1], q2, q3);
                unp2(acc[i][2], q4, q5); unp2(acc[i][3], q6, q7);
                float4* d = reinterpret_cast<float4*>(pp + (b20 + i) * 128);
                __stcg(d,     make_float4(q0, q1, q2, q3));
                __stcg(d + 1, make_float4(q4, q5, q6, q7));
            }
        }
        __syncthreads();
        if (tid == 0) {
            __threadfence();
            redrel(&g_pcnt[rank * 64]);
            const unsigned need = 32u * (unsigned)(t + 1);
            while (ldacq(&g_pcnt[rank * 64]) < need) {}
        }
        __syncthreads();

        // --- (8) P3: gather + cell update; publish h FIRST ---
        float4 hn = {0, 0, 0, 0};
        if (tid < 64) {
            const int bb = b0p + boff;
            float4 ai = {0,0,0,0}, af = {0,0,0,0}, ag = {0,0,0,0}, ao = {0,0,0,0};
            const float* pb = g_part[p] + bb * 128 + c4;
            #pragma unroll
            for (int q = 0; q < 8; ++q) {
                float4 v;
                v = __ldcg(reinterpret_cast<const float4*>(pb + (((0 * 8 + q) << 2) | rank) * 8192));
                ai.x += v.x; ai.y += v.y; ai.z += v.z; ai.w += v.w;
                v = __ldcg(reinterpret_cast<const float4*>(pb + (((1 * 8 + q) << 2) | rank) * 8192));
                af.x += v.x; af.y += v.y; af.z += v.z; af.w += v.w;
                v = __ldcg(reinterpret_cast<const float4*>(pb + (((2 * 8 + q) << 2) | rank) * 8192));
                ag.x += v.x; ag.y += v.y; ag.z += v.z; ag.w += v.w;
                v = __ldcg(reinterpret_cast<const float4*>(pb + (((3 * 8 + q) << 2) | rank) * 8192));
                ao.x += v.x; ao.y += v.y; ao.z += v.z; ao.w += v.w;
            }
            {
                float iv = sigf(ai.x + bi.x), fv = sigf(af.x + bf.x);
                float gv = tanhe(ag.x + bg4.x), ov = sigf(ao.x + bo.x);
                creg.x = fv * creg.x + iv * gv; hn.x = ov * tanhe(creg.x);
                iv = sigf(ai.y + bi.y); fv = sigf(af.y + bf.y);
                gv = tanhe(ag.y + bg4.y); ov = sigf(ao.y + bo.y);
                creg.y = fv * creg.y + iv * gv; hn.y = ov * tanhe(creg.y);
                iv = sigf(ai.z + bi.z); fv = sigf(af.z + bf.z);
                gv = tanhe(ag.z + bg4.z); ov = sigf(ao.z + bo.z);
                creg.z = fv * creg.z + iv * gv; hn.z = ov * tanhe(creg.z);
                iv = sigf(ai.w + bi.w); fv = sigf(af.w + bf.w);
                gv = tanhe(ag.w + bg4.w); ov = sigf(ao.w + bo.w);
                creg.w = fv * creg.w + iv * gv; hn.w = ov * tanhe(creg.w);
            }
            hlast = hn;
            __stcg(reinterpret_cast<float4*>(
                       &g_hbuf[pn][bb * 512 + rank * 128 + c4]), hn);
        }
        __syncthreads();
        if (tid == 0) {
            __threadfence();
            redrel(&g_hcnt[rank * 64]);
        }
        if (tid < 64) {   // hseq write AFTER the h publish
            const int bb = b0p + boff;
            *reinterpret_cast<float4*>(
                &out[bb * (512 * 512) + t * 512 + rank * 128 + c4]) = hn;
        }
    }

    if (tid < 64) {
        const int bb = b0p + boff;
        const int ccl = rank * 128 + c4;
        *reinterpret_cast<float4*>(&out[16777216 + bb * 512 + ccl]) = hlast;
        *reinterpret_cast<float4*>(&out[16777216 + 32768 + bb * 512 + ccl]) = creg;
    }
}

extern "C" void kernel_launch(void* const* d_in, const int* in_sizes, int n_in,
                              void* d_out, int out_size) {
    const float* x      = (const float*)d_in[0];
    const float* Ws     = (const float*)d_in[1];
    const float* Us     = (const float*)d_in[2];
    const float* biases = (const float*)d_in[3];
    const float* Wc     = (const float*)d_in[4];
    const float* bc     = (const float*)d_in[5];
    float* out = (float*)d_out;
    (void)in_sizes; (void)n_in; (void)out_size;

    zero_kernel<<<32, 256>>>();
    cudaFuncSetAttribute(slstm_kernel, cudaFuncAttributeMaxDynamicSharedMemorySize,
                         SMEM_BYTES);
    slstm_kernel<<<NCTA, NTHR, SMEM_BYTES>>>(x, Ws, Us, biases, Wc, bc, out);
}

// round 11
// speedup vs baseline: 1.3941x; 1.0868x over previous
#include <cuda_runtime.h>
#include <cstdint>

// SliceLSTM persistent kernel, round 11 = R10 + cp.async FIFO fix,
// full-width P3, fence removal.
// 128 CTAs x 256 threads, clusters of 4 = (gate, K-chunk), rank = tile.

#define NCTA 128
#define NTHR 256

typedef unsigned long long u64;

// shared layout (float offsets)
#define OFF_W1  0         // 192 x 16
#define OFF_B1  3072      // 16
#define OFF_W2  3088      // 64 x 128
#define OFF_X   11280     // [2 parity][64 b][68]  (x, b-major)
#define LDXR    68
#define XPAR    (64 * LDXR)
#define OFF_H   19984     // [64 b][132]           (h, b-major)
#define LDHR    132
#define OFF_ACT 28432     // [2 parity][64 c][68]  (act, k-major)
#define LDA     68
#define APAR    (64 * LDA)
#define SMEM_FLOATS 37136
#define SMEM_BYTES  (SMEM_FLOATS * 4)   // 145.1KB -> 1 CTA/SM

__device__ float g_hbuf[2][64 * 512];           // [parity][b][c]
__device__ float g_part[2][NCTA * 64 * 128];    // [parity][cta][b][cl]
__device__ unsigned g_pcnt[4 * 64];             // per tile, 256B apart
__device__ unsigned g_hcnt[4 * 64];

static __device__ __forceinline__ u64 pk2(float v) {
    u64 r; asm("mov.b64 %0, {%1, %1};" : "=l"(r) : "f"(v)); return r;
}
static __device__ __forceinline__ void unp2(u64 v, float& lo, float& hi) {
    asm("mov.b64 {%0, %1}, %2;" : "=f"(lo), "=f"(hi) : "l"(v));
}
static __device__ __forceinline__ void fma2(u64& d, u64 a, u64 b) {
    asm("fma.rn.f32x2 %0, %1, %2, %0;" : "+l"(d) : "l"(a), "l"(b));
}
static __device__ __forceinline__ float sigf(float x)  { return 1.0f / (1.0f + __expf(-x)); }
static __device__ __forceinline__ float tanhe(float x) {
    float e = __expf(2.0f * x);
    return 1.0f - 2.0f / (e + 1.0f);
}
static __device__ __forceinline__ unsigned ldacq(const unsigned* p) {
    unsigned v;
    asm volatile("ld.acquire.gpu.global.u32 %0, [%1];" : "=r"(v) : "l"(p) : "memory");
    return v;
}
static __device__ __forceinline__ void redrel(unsigned* p) {
    asm volatile("red.release.gpu.global.add.u32 [%0], 1;" :: "l"(p) : "memory");
}
static __device__ __forceinline__ uint32_t smem_u32(const void* p) {
    uint32_t a;
    asm("{ .reg .u64 t; cvta.to.shared.u64 t, %1; cvt.u32.u64 %0, t; }" : "=r"(a) : "l"(p));
    return a;
}
static __device__ __forceinline__ uint32_t mapa_rank(uint32_t addr, int rank) {
    uint32_t r;
    asm("mapa.shared::cluster.u32 %0, %1, %2;" : "=r"(r) : "r"(addr), "r"(rank));
    return r;
}
static __device__ __forceinline__ void st_cluster(uint32_t addr, float v) {
    asm volatile("st.shared::cluster.f32 [%0], %1;" :: "r"(addr), "f"(v) : "memory");
}
static __device__ __forceinline__ void cpasync16(uint32_t dst, const float* src) {
    asm volatile("cp.async.cg.shared.global [%0], [%1], 16;" :: "r"(dst), "l"(src) : "memory");
}
#define CP_COMMIT() asm volatile("cp.async.commit_group;" ::: "memory")
#define CP_WAIT0()  asm volatile("cp.async.wait_group 0;" ::: "memory")
#define CP_WAIT1()  asm volatile("cp.async.wait_group 1;" ::: "memory")
#define CP_WAIT2()  asm volatile("cp.async.wait_group 2;" ::: "memory")
#define CARRIVE() asm volatile("barrier.cluster.arrive.aligned;" ::: "memory")
#define CWAIT()   asm volatile("barrier.cluster.wait.aligned;" ::: "memory")

__global__ void zero_kernel() {
    int i = blockIdx.x * blockDim.x + threadIdx.x;
    int n = blockDim.x * gridDim.x;
    for (int j = i; j < 64 * 512; j += n) g_hbuf[0][j] = 0.0f;
    for (int j = i; j < 4 * 64; j += n) { g_pcnt[j] = 0u; g_hcnt[j] = 0u; }
}

__global__ void __launch_bounds__(NTHR, 1) __cluster_dims__(4, 1, 1)
slstm_kernel(const float* __restrict__ x,       // (64, 512, 256)
             const float* __restrict__ Ws,      // (4, 64, 512)
             const float* __restrict__ Us,      // (4, 128, 512)
             const float* __restrict__ biases,  // (4, 512)
             const float* __restrict__ Wc,      // (512, 2048)
             const float* __restrict__ bc,      // (2048,)
             float* __restrict__ out)           // hseq | h_t | c_t
{
    extern __shared__ float sm[];
    float* sW1  = sm + OFF_W1;
    float* sB1  = sm + OFF_B1;
    float* sW2  = sm + OFF_W2;
    float* sX   = sm + OFF_X;
    float* sH   = sm + OFF_H;
    float* sAct = sm + OFF_ACT;

    const int tid  = threadIdx.x;
    const int cta  = blockIdx.x;
    const int rank = cta & 3;
    const int clu  = cta >> 2;        // 0..31
    const int g2   = clu >> 3;        // gate
    const int kc   = clu & 7;         // connector K-chunk
    const int s1   = kc >> 1;         // input slice
    const int wcol0 = g2 * 128 + (kc & 1) * 64 + rank * 16;

    // P1 role: 1 batch x 4 cols per thread
    const int pab = tid >> 2;
    const int pac = tid & 3;
    // P2 role: 4 batches x 8 cols per thread
    const int b20 = (tid & 15) * 4;
    const int cg2 = tid >> 4;          // 0..15
    // P3 role: one (batch, col) per thread
    const int p3b  = clu * 2 + (tid >> 7);
    const int p3c  = tid & 127;
    const int colg = rank * 128 + p3c;

    // ---- persistent weights ----
    for (int i = tid; i < 192 * 16; i += NTHR) {
        int k = i >> 4, c = i & 15;
        sW1[i] = (k < 64) ? Ws[s1 * (64 * 512) + k * 512 + wcol0 + c]
                          : Us[s1 * (128 * 512) + (k - 64) * 512 + wcol0 + c];
    }
    if (tid < 16) sB1[tid] = biases[s1 * 512 + wcol0 + tid];
    for (int i = tid; i < 64 * 128; i += NTHR) {
        int k = i >> 7, c = i & 127;
        sW2[k * 128 + c] = Wc[(kc * 64 + k) * 2048 + g2 * 512 + rank * 128 + c];
    }

    // P3 biases + per-thread scalar state
    const float bci = bc[colg];
    const float bcf = bc[512 + colg];
    const float bcg = bc[1024 + colg];
    const float bco = bc[1536 + colg];
    float creg = 0.0f, hlast = 0.0f;

    const uint32_t xs_u32  = smem_u32(sX);
    const uint32_t hs_u32  = smem_u32(sH);
    const uint32_t act_u32 = smem_u32(sAct);
    uint32_t peer[4];
    #pragma unroll
    for (int r = 0; r < 4; ++r) peer[r] = mapa_rank(act_u32, r);

    // stage x(t=0) into parity 0
    {
        #pragma unroll
        for (int j = 0; j < 4; ++j) {
            int lin = tid + 256 * j;
            int b = lin & 63, q = lin >> 6;
            cpasync16(xs_u32 + (b * LDXR + q * 4) * 4,
                      &x[b * (512 * 256) + s1 * 64 + q * 4]);
        }
        CP_COMMIT();
        CP_WAIT0();
    }
    __syncthreads();

    for (int t = 0; t < 512; ++t) {
        const int p  = t & 1;
        const int pn = p ^ 1;

        // --- (1) wait h-flag ---
        if (tid == 0) {
            const unsigned need = 32u * (unsigned)t;
            while (ldacq(&g_hcnt[s1 * 64]) < need) {}
        }
        __syncthreads();

        // --- (2) commit h group (older), then x(t+1) group (newer) ---
        {
            const float* hb = g_hbuf[p];
            #pragma unroll
            for (int j = 0; j < 8; ++j) {
                int lin = tid + 256 * j;
                int b = lin & 63, q = lin >> 6;
                cpasync16(hs_u32 + (b * LDHR + q * 4) * 4,
                          &hb[b * 512 + s1 * 128 + q * 4]);
            }
        }
        CP_COMMIT();
        if (t + 1 < 512) {
            #pragma unroll
            for (int j = 0; j < 4; ++j) {
                int lin = tid + 256 * j;
                int b = lin & 63, q = lin >> 6;
                cpasync16(xs_u32 + (pn * XPAR + b * LDXR + q * 4) * 4,
                          &x[b * (512 * 256) + (t + 1) * 256 + s1 * 64 + q * 4]);
            }
        }
        CP_COMMIT();           // (possibly empty group at t=511)

        // --- (3) x(t) resident; P1 x-part ---
        CP_WAIT2();
        __syncthreads();
        u64 acc0 = 0ULL, acc1 = 0ULL;
        {
            const float* ap = sX + p * XPAR + pab * LDXR;
            const float* wp = sW1 + pac * 4;
            #pragma unroll 8
            for (int k = 0; k < 64; ++k) {
                const ulonglong2 w = *reinterpret_cast<const ulonglong2*>(wp + k * 16);
                const u64 a = pk2(ap[k]);
                fma2(acc0, a, w.x);
                fma2(acc1, a, w.y);
            }
        }

        // --- (4) h resident; P1 h-part + activation ---
        CP_WAIT1();            // h retired; x(t+1) may stay in flight
        __syncthreads();
        float v0, v1, v2, v3;
        {
            const float* ap = sH + pab * LDHR;
            const float* wp = sW1 + pac * 4;
            #pragma unroll 8
            for (int k = 0; k < 128; ++k) {
                const ulonglong2 w = *reinterpret_cast<const ulonglong2*>(wp + (64 + k) * 16);
                const u64 a = pk2(ap[k]);
                fma2(acc0, a, w.x);
                fma2(acc1, a, w.y);
            }
            unp2(acc0, v0, v1);
            unp2(acc1, v2, v3);
            v0 += sB1[pac * 4 + 0];
            v1 += sB1[pac * 4 + 1];
            v2 += sB1[pac * 4 + 2];
            v3 += sB1[pac * 4 + 3];
            if (g2 == 2) { v0 = tanhe(v0); v1 = tanhe(v1); v2 = tanhe(v2); v3 = tanhe(v3); }
            else         { v0 = sigf(v0);  v1 = sigf(v1);  v2 = sigf(v2);  v3 = sigf(v3);  }
        }

        // --- (5) act publish local + remote, one cluster barrier ---
        {
            const int lc = rank * 16 + pac * 4;
            const int base = p * APAR + lc * LDA + pab;
            sAct[base]           = v0;
            sAct[base + LDA]     = v1;
            sAct[base + 2 * LDA] = v2;
            sAct[base + 3 * LDA] = v3;
            const uint32_t off = (uint32_t)base * 4;
            #pragma unroll
            for (int r = 0; r < 4; ++r) {
                if (r == rank) continue;
                const uint32_t ra = peer[r] + off;
                st_cluster(ra,               v0);
                st_cluster(ra + 4 * LDA,     v1);
                st_cluster(ra + 8 * LDA,     v2);
                st_cluster(ra + 12 * LDA,    v3);
            }
        }
        CARRIVE();
        CWAIT();

        // --- (6) P2 connector GEMM ---
        {
            u64 acc[4][4];
            #pragma unroll
            for (int i = 0; i < 4; ++i)
                #pragma unroll
                for (int j = 0; j < 4; ++j) acc[i][j] = 0ULL;
            const float* ab = sAct + p * APAR;
            const float* wb = sW2 + cg2 * 8;
            #pragma unroll 4
            for (int k = 0; k < 64; ++k) {
                const float4 a4 = *reinterpret_cast<const float4*>(&ab[k * LDA + b20]);
                const ulonglong2 wA = *reinterpret_cast<const ulonglong2*>(&wb[k * 128]);
                const ulonglong2 wB = *reinterpret_cast<const ulonglong2*>(&wb[k * 128 + 4]);
                const u64 a0 = pk2(a4.x);
                const u64 a1 = pk2(a4.y);
                const u64 a2 = pk2(a4.z);
                const u64 a3 = pk2(a4.w);
                fma2(acc[0][0], a0, wA.x); fma2(acc[0][1], a0, wA.y);
                fma2(acc[0][2], a0, wB.x); fma2(acc[0][3], a0, wB.y);
                fma2(acc[1][0], a1, wA.x); fma2(acc[1][1], a1, wA.y);
                fma2(acc[1][2], a1, wB.x); fma2(acc[1][3], a1, wB.y);
                fma2(acc[2][0], a2, wA.x); fma2(acc[2][1], a2, wA.y);
                fma2(acc[2][2], a2, wB.x); fma2(acc[2][3], a2, wB.y);
                fma2(acc[3][0], a3, wA.x); fma2(acc[3][1], a3, wA.y);
                fma2(acc[3][2], a3, wB.x); fma2(acc[3][3], a3, wB.y);
            }
            float* pp = g_part[p] + cta * 8192 + cg2 * 8;
            #pragma unroll
            for (int i = 0; i < 4; ++i) {
                float q0, q1, q2, q3, q4, q5, q6, q7;
                unp2(acc[i][0], q0, q1); unp2(acc[i][1], q2, q3);
                unp2(acc[i][2], q4, q5); unp2(acc[i][3], q6, q7);
                float4* d = reinterpret_cast<float4*>(pp + (b20 + i) * 128);
                __stcg(d,     make_float4(q0, q1, q2, q3));
                __stcg(d + 1, make_float4(q4, q5, q6, q7));
            }
        }
        __syncthreads();
        if (tid == 0) {
            redrel(&g_pcnt[rank * 64]);
            const unsigned need = 32u * (unsigned)(t + 1);
            while (ldacq(&g_pcnt[rank * 64]) < need) {}
        }
        __syncthreads();

        // --- (7) P3 on ALL 256 threads: one (b,c) each ---
        {
            float a0 = bci, a1 = bcf, a2 = bcg, a3 = bco;
            const float* gp = g_part[p] + p3b * 128 + p3c;
            #pragma unroll
            for (int q = 0; q < 8; ++q) {
                a0 += __ldcg(gp + (( 0 + q) * 4 + rank) * 8192);
                a1 += __ldcg(gp + (( 8 + q) * 4 + rank) * 8192);
                a2 += __ldcg(gp + ((16 + q) * 4 + rank) * 8192);
                a3 += __ldcg(gp + ((24 + q) * 4 + rank) * 8192);
            }
            const float iv = sigf(a0);
            const float fv = sigf(a1);
            const float gv = tanhe(a2);
            const float ov = sigf(a3);
            creg = fv * creg + iv * gv;
            const float hn = ov * tanhe(creg);
            hlast = hn;
            __stcg(&g_hbuf[pn][p3b * 512 + colg], hn);
            __syncthreads();
            if (tid == 0) redrel(&g_hcnt[rank * 64]);
            out[p3b * (512 * 512) + t * 512 + colg] = hn;
        }
    }

    out[16777216 + p3b * 512 + colg] = hlast;
    out[16777216 + 32768 + p3b * 512 + colg] = creg;
}

extern "C" void kernel_launch(void* const* d_in, const int* in_sizes, int n_in,
                              void* d_out, int out_size) {
    const float* x      = (const float*)d_in[0];
    const float* Ws     = (const float*)d_in[1];
    const float* Us     = (const float*)d_in[2];
    const float* biases = (const float*)d_in[3];
    const float* Wc     = (const float*)d_in[4];
    const float* bc     = (const float*)d_in[5];
    float* out = (float*)d_out;
    (void)in_sizes; (void)n_in; (void)out_size;

    zero_kernel<<<32, 256>>>();
    cudaFuncSetAttribute(slstm_kernel, cudaFuncAttributeMaxDynamicSharedMemorySize,
                         SMEM_BYTES);
    slstm_kernel<<<NCTA, NTHR, SMEM_BYTES>>>(x, Ws, Us, biases, Wc, bc, out);
}